// round 3
// baseline (speedup 1.0000x reference)
#include <cuda_runtime.h>

#define MAXN 100000
#define MAXE 1600000
#define HIDF 64

// ---------------- static device scratch (no allocations allowed) ----------------
__device__ float d_hw[(size_t)MAXN * HIDF];     // GEMM output / gather source
__device__ float d_hbuf[(size_t)MAXN * HIDF];   // aggregated / normalized features
__device__ int   d_cnt[MAXN];                   // in-degree histogram (excl. self loop)
__device__ int   d_fill[MAXN];                  // scatter fill counters
__device__ int   d_off[MAXN + 1];               // CSR row offsets (by dst)
__device__ float d_dinv[MAXN];                  // deg^{-1/2}
__device__ int2  d_csr[MAXE];                   // {src, norm as float bits}
__device__ int   d_bsum[256];
__device__ int   d_boff[256];
__device__ float d_stats[128];                  // sum[64], sumsq[64]

// ---------------- CSR construction ----------------
__global__ void zero_kernel(int N) {
    int i = blockIdx.x * blockDim.x + threadIdx.x;
    if (i < N) { d_cnt[i] = 0; d_fill[i] = 0; }
}

__global__ void hist_kernel(const int* __restrict__ dst, int E) {
    int i = blockIdx.x * blockDim.x + threadIdx.x;
    if (i < E) atomicAdd(&d_cnt[dst[i]], 1);
}

__global__ void dinv_kernel(int N) {
    int i = blockIdx.x * blockDim.x + threadIdx.x;
    if (i < N) d_dinv[i] = rsqrtf((float)(d_cnt[i] + 1));   // +1 self loop
}

// scanA: per-1024-chunk sums
__global__ void scanA_kernel(int N) {
    __shared__ int sh[256];
    int base = blockIdx.x * 1024 + threadIdx.x * 4;
    int t = 0;
#pragma unroll
    for (int j = 0; j < 4; j++) { int i = base + j; if (i < N) t += d_cnt[i]; }
    sh[threadIdx.x] = t;
    __syncthreads();
    for (int o = 128; o > 0; o >>= 1) {
        if (threadIdx.x < o) sh[threadIdx.x] += sh[threadIdx.x + o];
        __syncthreads();
    }
    if (threadIdx.x == 0) d_bsum[blockIdx.x] = sh[0];
}

// scanB: exclusive scan of block sums (tiny, single thread); writes off[N]
__global__ void scanB_kernel(int G, int N) {
    if (threadIdx.x == 0 && blockIdx.x == 0) {
        int run = 0;
        for (int b = 0; b < G; b++) { d_boff[b] = run; run += d_bsum[b]; }
        d_off[N] = run;
    }
}

// scanC: local exclusive scan + block offset -> d_off
__global__ void scanC_kernel(int N) {
    __shared__ int sh[256];
    int tid = threadIdx.x;
    int base = blockIdx.x * 1024 + tid * 4;
    int v[4]; int t = 0;
#pragma unroll
    for (int j = 0; j < 4; j++) { v[j] = (base + j < N) ? d_cnt[base + j] : 0; t += v[j]; }
    sh[tid] = t;
    __syncthreads();
    for (int o = 1; o < 256; o <<= 1) {
        int x = (tid >= o) ? sh[tid - o] : 0;
        __syncthreads();
        sh[tid] += x;
        __syncthreads();
    }
    int excl = sh[tid] - t + d_boff[blockIdx.x];
#pragma unroll
    for (int j = 0; j < 4; j++) {
        if (base + j < N) { d_off[base + j] = excl; excl += v[j]; }
    }
}

__global__ void scatter_kernel(const int* __restrict__ src,
                               const int* __restrict__ dst, int E) {
    int i = blockIdx.x * blockDim.x + threadIdx.x;
    if (i >= E) return;
    int s = src[i];
    int d = dst[i];
    int pos = d_off[d] + atomicAdd(&d_fill[d], 1);
    float w = d_dinv[s] * d_dinv[d];
    d_csr[pos] = make_int2(s, __float_as_int(w));
}

// ---------------- tiled fp32 GEMM: d_hw[M,NC] = A[M,K] @ W[K,NC] ----------------
// USE_X: A = external pointer (first layer x); else A = d_hbuf.
// MLPE: fused bias + relu epilogue. ZS: block 0 zeroes d_stats.
template <int K, int NC, bool MLPE, bool ZS, bool USE_X>
__global__ void gemm_kernel(const float* __restrict__ A_ext, const float* __restrict__ Wm,
                            const float* __restrict__ bias, int M) {
    constexpr int CG = NC / 4;        // column groups (float4)
    constexpr int TY = 256 / CG;      // row groups
    constexpr int TM = TY * 4;        // tile rows
    __shared__ float Xs[TM][68];      // padded rows
    __shared__ float Ws[64][NC];

    const float* A = USE_X ? A_ext : d_hbuf;
    float* out = d_hw;

    int tid = threadIdx.x;
    if (ZS && blockIdx.x == 0 && tid < 128) d_stats[tid] = 0.f;

    int m0 = blockIdx.x * TM;
    int tx = tid % CG;
    int ty = tid / CG;
    float acc[4][4] = {};

    for (int kc = 0; kc < K; kc += 64) {
        for (int i = tid; i < 64 * NC / 4; i += 256)
            ((float4*)Ws)[i] = ((const float4*)(Wm + (size_t)kc * NC))[i];
        for (int i = tid; i < TM * 16; i += 256) {
            int r = i / 16, k4 = i % 16;
            int row = m0 + r;
            float4 v = make_float4(0.f, 0.f, 0.f, 0.f);
            if (row < M) v = *(const float4*)(A + (size_t)row * K + kc + k4 * 4);
            *(float4*)(&Xs[r][k4 * 4]) = v;
        }
        __syncthreads();
#pragma unroll 8
        for (int k = 0; k < 64; k++) {
            float4 w = *(const float4*)(&Ws[k][tx * 4]);
#pragma unroll
            for (int i = 0; i < 4; i++) {
                float xv = Xs[ty * 4 + i][k];
                acc[i][0] = fmaf(xv, w.x, acc[i][0]);
                acc[i][1] = fmaf(xv, w.y, acc[i][1]);
                acc[i][2] = fmaf(xv, w.z, acc[i][2]);
                acc[i][3] = fmaf(xv, w.w, acc[i][3]);
            }
        }
        __syncthreads();
    }
    int c0 = tx * 4;
#pragma unroll
    for (int i = 0; i < 4; i++) {
        int row = m0 + ty * 4 + i;
        if (row < M) {
            float4 v = make_float4(acc[i][0], acc[i][1], acc[i][2], acc[i][3]);
            if (MLPE) {
                v.x = fmaxf(v.x + bias[c0 + 0], 0.f);
                v.y = fmaxf(v.y + bias[c0 + 1], 0.f);
                v.z = fmaxf(v.z + bias[c0 + 2], 0.f);
                v.w = fmaxf(v.w + bias[c0 + 3], 0.f);
            }
            *(float4*)(out + (size_t)row * NC + c0) = v;
        }
    }
}

// ---------------- aggregation: warp per node, gather over CSR + fused BN stats ----------------
// reads d_hw, writes d_hbuf
__global__ void agg_kernel(int N) {
    __shared__ float s_sum[8][64];
    __shared__ float s_sq[8][64];
    const float2* hw2 = (const float2*)d_hw;
    float2* out2 = (float2*)d_hbuf;
    int warp = threadIdx.x >> 5;
    int lane = threadIdx.x & 31;
    int node = blockIdx.x * 8 + warp;
    float2 acc = make_float2(0.f, 0.f);
    if (node < N) {
        float dv = d_dinv[node];
        float sw = dv * dv;
        float2 v0 = hw2[(size_t)node * 32 + lane];
        acc.x = v0.x * sw;
        acc.y = v0.y * sw;
        int s = d_off[node], e = d_off[node + 1];
        for (int i = s; i < e; i++) {
            int2 ed = d_csr[i];
            float w = __int_as_float(ed.y);
            float2 v = hw2[(size_t)ed.x * 32 + lane];
            acc.x = fmaf(w, v.x, acc.x);
            acc.y = fmaf(w, v.y, acc.y);
        }
        out2[(size_t)node * 32 + lane] = acc;
    }
    s_sum[warp][2 * lane]     = acc.x;
    s_sum[warp][2 * lane + 1] = acc.y;
    s_sq[warp][2 * lane]      = acc.x * acc.x;
    s_sq[warp][2 * lane + 1]  = acc.y * acc.y;
    __syncthreads();
    if (threadIdx.x < 64) {
        int c = threadIdx.x;
        float t = 0.f, q = 0.f;
#pragma unroll
        for (int w = 0; w < 8; w++) { t += s_sum[w][c]; q += s_sq[w][c]; }
        atomicAdd(&d_stats[c], t);
        atomicAdd(&d_stats[64 + c], q);
    }
}

// ---------------- BatchNorm (train-mode batch stats) + ReLU, in place on d_hbuf ----------------
__global__ void bn_kernel(const float* __restrict__ g, const float* __restrict__ bt, int N) {
    int idx = blockIdx.x * blockDim.x + threadIdx.x;   // over N*16 float4
    if (idx >= N * 16) return;
    float* h = d_hbuf;
    int c0 = (idx & 15) * 4;
    float invn = 1.f / (float)N;
    float4 v = ((const float4*)h)[idx];
    float r[4] = {v.x, v.y, v.z, v.w};
#pragma unroll
    for (int j = 0; j < 4; j++) {
        int c = c0 + j;
        float mu  = d_stats[c] * invn;
        float var = d_stats[64 + c] * invn - mu * mu;
        float sc  = rsqrtf(var + 1e-5f) * g[c];
        float sh  = bt[c] - mu * sc;
        r[j] = fmaxf(fmaf(r[j], sc, sh), 0.f);
    }
    ((float4*)h)[idx] = make_float4(r[0], r[1], r[2], r[3]);
}

// ---------------- final dot: out[n] = d_hw[n,:32] . lw2 + lb2 ----------------
__global__ void dot_kernel(const float* __restrict__ lw2,
                           const float* __restrict__ lb2, float* __restrict__ out, int N) {
    int gw = (blockIdx.x * blockDim.x + threadIdx.x) >> 5;
    int lane = threadIdx.x & 31;
    if (gw >= N) return;
    float v = d_hw[(size_t)gw * 32 + lane] * lw2[lane];
#pragma unroll
    for (int o = 16; o > 0; o >>= 1) v += __shfl_down_sync(0xffffffffu, v, o);
    if (lane == 0) out[gw] = v + lb2[0];
}

// ---------------- host orchestration (kernel launches ONLY) ----------------
extern "C" void kernel_launch(void* const* d_in, const int* in_sizes, int n_in,
                              void* d_out, int out_size) {
    const float* x   = (const float*)d_in[0];
    const int*   ei  = (const int*)d_in[1];     // JAX canonicalizes int64 -> int32
    const float* W0  = (const float*)d_in[2];
    const float* g0  = (const float*)d_in[4];
    const float* bt0 = (const float*)d_in[5];
    const float* W1  = (const float*)d_in[6];
    const float* g1  = (const float*)d_in[8];
    const float* bt1 = (const float*)d_in[9];
    const float* W2  = (const float*)d_in[10];
    const float* g2  = (const float*)d_in[12];
    const float* bt2 = (const float*)d_in[13];
    const float* lw1 = (const float*)d_in[14];
    const float* lb1 = (const float*)d_in[15];
    const float* lw2 = (const float*)d_in[16];
    const float* lb2 = (const float*)d_in[17];
    float* out = (float*)d_out;

    int N = out_size;                 // 100000
    int E = in_sizes[1] / 2;          // 1600000
    if (N > MAXN || E > MAXE) return;

    const int* src = ei;
    const int* dst = ei + E;

    // ---- CSR build (per call; graph is an input) ----
    int bN = (N + 255) / 256;
    int bE = (E + 255) / 256;
    int G  = (N + 1023) / 1024;
    zero_kernel<<<bN, 256>>>(N);
    hist_kernel<<<bE, 256>>>(dst, E);
    dinv_kernel<<<bN, 256>>>(N);
    scanA_kernel<<<G, 256>>>(N);
    scanB_kernel<<<1, 32>>>(G, N);
    scanC_kernel<<<G, 256>>>(N);
    scatter_kernel<<<bE, 256>>>(src, dst, E);

    int gemmM64 = (N + 63) / 64;
    int aggB    = (N + 7) / 8;
    int bnB     = (N * 16 + 255) / 256;

    // ---- layer 0: x[N,128] @ W0 -> d_hw; aggregate -> d_hbuf; BN+ReLU ----
    gemm_kernel<128, 64, false, true, true><<<gemmM64, 256>>>(x, W0, nullptr, N);
    agg_kernel<<<aggB, 256>>>(N);
    bn_kernel<<<bnB, 256>>>(g0, bt0, N);

    // ---- layer 1 ----
    gemm_kernel<64, 64, false, true, false><<<gemmM64, 256>>>(nullptr, W1, nullptr, N);
    agg_kernel<<<aggB, 256>>>(N);
    bn_kernel<<<bnB, 256>>>(g1, bt1, N);

    // ---- layer 2 ----
    gemm_kernel<64, 64, false, true, false><<<gemmM64, 256>>>(nullptr, W2, nullptr, N);
    agg_kernel<<<aggB, 256>>>(N);
    bn_kernel<<<bnB, 256>>>(g2, bt2, N);

    // ---- MLP head: relu(d_hbuf @ lw1 + lb1) -> d_hw[N,32]; dot with lw2 -> out ----
    int gemmM128 = (N + 127) / 128;
    gemm_kernel<64, 32, true, false, false><<<gemmM128, 256>>>(nullptr, lw1, lb1, N);
    int dotB = (N + 7) / 8;
    dot_kernel<<<dotB, 256>>>(lw2, lb2, out, N);
}

// round 4
// speedup vs baseline: 1.0214x; 1.0214x over previous
#include <cuda_runtime.h>

#define MAXN 100000
#define MAXE 1600000
#define HIDF 64

// ---------------- static device scratch ----------------
__device__ __align__(16) float d_hw[(size_t)MAXN * HIDF];    // GEMM out / gather source
__device__ __align__(16) float d_hbuf[(size_t)MAXN * HIDF];  // raw aggregated features
__device__ int   d_cnt[MAXN];
__device__ int   d_fill[MAXN];
__device__ int   d_off[MAXN + 1];
__device__ float d_dinv[MAXN];
__device__ int2  d_csr[MAXE];
__device__ int   d_bsum[256];
__device__ int   d_boff[256];
__device__ float d_stats[256];      // two buffers of 128: [sum64|sumsq64] x2

// ---------------- CSR construction ----------------
__global__ void zero_kernel(int N) {
    int i = blockIdx.x * blockDim.x + threadIdx.x;
    if (i < N) d_cnt[i] = 0;
}

__global__ void hist_kernel(const int* __restrict__ dst, int E) {
    int i = blockIdx.x * blockDim.x + threadIdx.x;
    if (i < E) atomicAdd(&d_cnt[dst[i]], 1);
}

// per-1024-chunk sums + fused dinv
__global__ void scanA_kernel(int N) {
    __shared__ int sh[256];
    int base = blockIdx.x * 1024 + threadIdx.x * 4;
    int t = 0;
#pragma unroll
    for (int j = 0; j < 4; j++) {
        int i = base + j;
        if (i < N) {
            int c = d_cnt[i];
            t += c;
            d_dinv[i] = rsqrtf((float)(c + 1));   // +1 self loop
        }
    }
    sh[threadIdx.x] = t;
    __syncthreads();
    for (int o = 128; o > 0; o >>= 1) {
        if (threadIdx.x < o) sh[threadIdx.x] += sh[threadIdx.x + o];
        __syncthreads();
    }
    if (threadIdx.x == 0) d_bsum[blockIdx.x] = sh[0];
}

__global__ void scanB_kernel(int G, int N) {
    if (threadIdx.x == 0 && blockIdx.x == 0) {
        int run = 0;
        for (int b = 0; b < G; b++) { d_boff[b] = run; run += d_bsum[b]; }
        d_off[N] = run;
    }
}

// local exclusive scan + block offset; also zeroes d_fill
__global__ void scanC_kernel(int N) {
    __shared__ int sh[256];
    int tid = threadIdx.x;
    int base = blockIdx.x * 1024 + tid * 4;
    int v[4]; int t = 0;
#pragma unroll
    for (int j = 0; j < 4; j++) { v[j] = (base + j < N) ? d_cnt[base + j] : 0; t += v[j]; }
    sh[tid] = t;
    __syncthreads();
    for (int o = 1; o < 256; o <<= 1) {
        int x = (tid >= o) ? sh[tid - o] : 0;
        __syncthreads();
        sh[tid] += x;
        __syncthreads();
    }
    int excl = sh[tid] - t + d_boff[blockIdx.x];
#pragma unroll
    for (int j = 0; j < 4; j++) {
        if (base + j < N) { d_off[base + j] = excl; d_fill[base + j] = 0; excl += v[j]; }
    }
}

__global__ void scatter_kernel(const int* __restrict__ src,
                               const int* __restrict__ dst, int E) {
    int i = blockIdx.x * blockDim.x + threadIdx.x;
    if (i >= E) return;
    int s = src[i];
    int d = dst[i];
    int pos = d_off[d] + atomicAdd(&d_fill[d], 1);
    float w = d_dinv[s] * d_dinv[d];
    d_csr[pos] = make_int2(s, __float_as_int(w));
}

// ---------------- GEMM: 128-row tile, 8x(NC/8) thread tile, transposed-X smem ----------------
// A[M,K] @ W[K,NC]. BNIN: normalize+relu A on load using d_stats[bnoff] + g/bt.
// zsoff>=0: block 0 zeroes d_stats[zsoff..+127]. DOT: fused bias+relu+dot epilogue -> out[M].
// !DOT: writes d_hw[M,NC].
template <int K, int NC, bool USE_X, bool BNIN, bool DOT>
__global__ void gemm_kernel(const float* __restrict__ A_ext, const float* __restrict__ Wm,
                            const float* __restrict__ g, const float* __restrict__ bt,
                            const float* __restrict__ lb1, const float* __restrict__ lw2,
                            const float* __restrict__ lb2, float* __restrict__ out,
                            int M, int bnoff, int zsoff) {
    constexpr int CH = 32;            // k-chunk
    constexpr int NCc = NC / 8;       // cols per thread (8 or 4)
    __shared__ __align__(16) float Xs[CH][128];   // k-major, conflict-free both ways
    __shared__ __align__(16) float Ws[CH][NC];
    __shared__ float s_sc[64], s_sh[64];

    int tid = threadIdx.x;            // 128 threads
    if (zsoff >= 0 && blockIdx.x == 0) d_stats[zsoff + tid] = 0.f;

    if (BNIN && tid < 64) {
        float invM = 1.f / (float)M;
        float mu  = d_stats[bnoff + tid] * invM;
        float var = d_stats[bnoff + 64 + tid] * invM - mu * mu;
        float sc  = rsqrtf(var + 1e-5f) * g[tid];
        s_sc[tid] = sc;
        s_sh[tid] = bt[tid] - mu * sc;
    }
    if (BNIN) __syncthreads();

    const float* A = USE_X ? A_ext : d_hbuf;
    int m0 = blockIdx.x * 128;
    int row = m0 + tid;
    bool rv = row < M;
    int tx = tid % 8;
    int ty = tid / 8;
    float acc[8][NCc] = {};

    for (int kc = 0; kc < K; kc += CH) {
        // fill W chunk (row-major, coalesced)
#pragma unroll
        for (int i = tid; i < CH * NC / 4; i += 128)
            ((float4*)Ws)[i] = ((const float4*)(Wm + (size_t)kc * NC))[i];
        // fill X chunk transposed: thread = one row; smem stores conflict-free (bank = tid)
#pragma unroll
        for (int k4 = 0; k4 < CH / 4; k4++) {
            float4 a = rv ? *(const float4*)(A + (size_t)row * K + kc + k4 * 4)
                          : make_float4(0.f, 0.f, 0.f, 0.f);
            if (BNIN) {
                int c = kc + k4 * 4;
                a.x = fmaxf(fmaf(a.x, s_sc[c + 0], s_sh[c + 0]), 0.f);
                a.y = fmaxf(fmaf(a.y, s_sc[c + 1], s_sh[c + 1]), 0.f);
                a.z = fmaxf(fmaf(a.z, s_sc[c + 2], s_sh[c + 2]), 0.f);
                a.w = fmaxf(fmaf(a.w, s_sc[c + 3], s_sh[c + 3]), 0.f);
            }
            Xs[k4 * 4 + 0][tid] = a.x;
            Xs[k4 * 4 + 1][tid] = a.y;
            Xs[k4 * 4 + 2][tid] = a.z;
            Xs[k4 * 4 + 3][tid] = a.w;
        }
        __syncthreads();
#pragma unroll 8
        for (int k = 0; k < CH; k++) {
            float xv[8];
            *(float4*)&xv[0] = *(const float4*)&Xs[k][ty * 8];
            *(float4*)&xv[4] = *(const float4*)&Xs[k][ty * 8 + 4];
            float wv[NCc];
            *(float4*)&wv[0] = *(const float4*)&Ws[k][tx * NCc];
            if (NCc == 8)
                *(float4*)&wv[4] = *(const float4*)&Ws[k][tx * NCc + 4];
#pragma unroll
            for (int i = 0; i < 8; i++)
#pragma unroll
                for (int j = 0; j < NCc; j++)
                    acc[i][j] = fmaf(xv[i], wv[j], acc[i][j]);
        }
        __syncthreads();
    }

    if (!DOT) {
        int c0 = tx * NCc;
#pragma unroll
        for (int i = 0; i < 8; i++) {
            int r = m0 + ty * 8 + i;
            if (r < M) {
                *(float4*)(d_hw + (size_t)r * NC + c0) =
                    make_float4(acc[i][0], acc[i][1], acc[i][2], acc[i][3]);
                if (NCc == 8)
                    *(float4*)(d_hw + (size_t)r * NC + c0 + 4) =
                        make_float4(acc[i][4], acc[i][5], acc[i][6], acc[i][7]);
            }
        }
    } else {
        int c0 = tx * NCc;   // NCc==4 here
        float lb[4], lw[4];
#pragma unroll
        for (int j = 0; j < 4; j++) { lb[j] = lb1[c0 + j]; lw[j] = lw2[c0 + j]; }
        float lbias = lb2[0];
#pragma unroll
        for (int i = 0; i < 8; i++) {
            float p = 0.f;
#pragma unroll
            for (int j = 0; j < 4; j++)
                p = fmaf(fmaxf(acc[i][j] + lb[j], 0.f), lw[j], p);
            p += __shfl_down_sync(0xffffffffu, p, 4, 8);
            p += __shfl_down_sync(0xffffffffu, p, 2, 8);
            p += __shfl_down_sync(0xffffffffu, p, 1, 8);
            if (tx == 0) {
                int r = m0 + ty * 8 + i;
                if (r < M) out[r] = p + lbias;
            }
        }
    }
}

// ---------------- aggregation: warp per node, unroll-4 gather + fused BN stats ----------------
__global__ void agg_kernel(int N, int sb) {
    __shared__ float s_sum[8][64];
    __shared__ float s_sq[8][64];
    const float2* hw2 = (const float2*)d_hw;
    float2* out2 = (float2*)d_hbuf;
    int warp = threadIdx.x >> 5;
    int lane = threadIdx.x & 31;
    int node = blockIdx.x * 8 + warp;
    float2 acc = make_float2(0.f, 0.f);
    if (node < N) {
        float dv = d_dinv[node];
        float sw = dv * dv;
        float2 v0 = hw2[(size_t)node * 32 + lane];
        acc.x = v0.x * sw;
        acc.y = v0.y * sw;
        int s = d_off[node], e = d_off[node + 1];
        int i = s;
        int e4 = s + ((e - s) & ~3);
        for (; i < e4; i += 4) {
            int2 c0 = d_csr[i];
            int2 c1 = d_csr[i + 1];
            int2 c2 = d_csr[i + 2];
            int2 c3 = d_csr[i + 3];
            float2 v0_ = hw2[(size_t)c0.x * 32 + lane];
            float2 v1_ = hw2[(size_t)c1.x * 32 + lane];
            float2 v2_ = hw2[(size_t)c2.x * 32 + lane];
            float2 v3_ = hw2[(size_t)c3.x * 32 + lane];
            acc.x = fmaf(__int_as_float(c0.y), v0_.x, acc.x);
            acc.y = fmaf(__int_as_float(c0.y), v0_.y, acc.y);
            acc.x = fmaf(__int_as_float(c1.y), v1_.x, acc.x);
            acc.y = fmaf(__int_as_float(c1.y), v1_.y, acc.y);
            acc.x = fmaf(__int_as_float(c2.y), v2_.x, acc.x);
            acc.y = fmaf(__int_as_float(c2.y), v2_.y, acc.y);
            acc.x = fmaf(__int_as_float(c3.y), v3_.x, acc.x);
            acc.y = fmaf(__int_as_float(c3.y), v3_.y, acc.y);
        }
        for (; i < e; i++) {
            int2 ed = d_csr[i];
            float w = __int_as_float(ed.y);
            float2 v = hw2[(size_t)ed.x * 32 + lane];
            acc.x = fmaf(w, v.x, acc.x);
            acc.y = fmaf(w, v.y, acc.y);
        }
        out2[(size_t)node * 32 + lane] = acc;
    }
    s_sum[warp][2 * lane]     = acc.x;
    s_sum[warp][2 * lane + 1] = acc.y;
    s_sq[warp][2 * lane]      = acc.x * acc.x;
    s_sq[warp][2 * lane + 1]  = acc.y * acc.y;
    __syncthreads();
    if (threadIdx.x < 64) {
        int c = threadIdx.x;
        float t = 0.f, q = 0.f;
#pragma unroll
        for (int w = 0; w < 8; w++) { t += s_sum[w][c]; q += s_sq[w][c]; }
        atomicAdd(&d_stats[sb + c], t);
        atomicAdd(&d_stats[sb + 64 + c], q);
    }
}

// ---------------- host orchestration (kernel launches ONLY) ----------------
extern "C" void kernel_launch(void* const* d_in, const int* in_sizes, int n_in,
                              void* d_out, int out_size) {
    const float* x   = (const float*)d_in[0];
    const int*   ei  = (const int*)d_in[1];
    const float* W0  = (const float*)d_in[2];
    const float* g0  = (const float*)d_in[4];
    const float* bt0 = (const float*)d_in[5];
    const float* W1  = (const float*)d_in[6];
    const float* g1  = (const float*)d_in[8];
    const float* bt1 = (const float*)d_in[9];
    const float* W2  = (const float*)d_in[10];
    const float* g2  = (const float*)d_in[12];
    const float* bt2 = (const float*)d_in[13];
    const float* lw1 = (const float*)d_in[14];
    const float* lb1 = (const float*)d_in[15];
    const float* lw2 = (const float*)d_in[16];
    const float* lb2 = (const float*)d_in[17];
    float* out = (float*)d_out;

    int N = out_size;
    int E = in_sizes[1] / 2;
    if (N > MAXN || E > MAXE) return;

    const int* src = ei;
    const int* dst = ei + E;

    int bN = (N + 255) / 256;
    int bE = (E + 255) / 256;
    int G  = (N + 1023) / 1024;
    zero_kernel<<<bN, 256>>>(N);
    hist_kernel<<<bE, 256>>>(dst, E);
    scanA_kernel<<<G, 256>>>(N);
    scanB_kernel<<<1, 32>>>(G, N);
    scanC_kernel<<<G, 256>>>(N);
    scatter_kernel<<<bE, 256>>>(src, dst, E);

    int gB   = (N + 127) / 128;
    int aggB = (N + 7) / 8;

    // L0: x @ W0 -> hw (zero stats buf0); agg -> hbuf + stats buf0
    gemm_kernel<128, 64, true, false, false><<<gB, 128>>>(
        x, W0, nullptr, nullptr, nullptr, nullptr, nullptr, nullptr, N, 0, 0);
    agg_kernel<<<aggB, 256>>>(N, 0);

    // L1: BN0(hbuf) @ W1 -> hw (zero buf1); agg -> stats buf1
    gemm_kernel<64, 64, false, true, false><<<gB, 128>>>(
        nullptr, W1, g0, bt0, nullptr, nullptr, nullptr, nullptr, N, 0, 128);
    agg_kernel<<<aggB, 256>>>(N, 128);

    // L2: BN1(hbuf) @ W2 -> hw (zero buf0); agg -> stats buf0
    gemm_kernel<64, 64, false, true, false><<<gB, 128>>>(
        nullptr, W2, g1, bt1, nullptr, nullptr, nullptr, nullptr, N, 128, 0);
    agg_kernel<<<aggB, 256>>>(N, 0);

    // MLP head fused: relu(BN2(hbuf) @ lw1 + lb1) . lw2 + lb2 -> out
    gemm_kernel<64, 32, false, true, true><<<gB, 128>>>(
        nullptr, lw1, g2, bt2, lb1, lw2, lb2, out, N, 0, -1);
}

// round 5
// speedup vs baseline: 1.1519x; 1.1278x over previous
#include <cuda_runtime.h>
#include <cuda_fp16.h>

#define MAXN 100000
#define MAXE 1600000
#define HIDF 64

// ---------------- static device scratch ----------------
__device__ __align__(16) float d_hw[(size_t)MAXN * HIDF];    // holds fp16 rows (N x 64 halves)
__device__ __align__(16) float d_hbuf[(size_t)MAXN * HIDF];  // raw aggregated features fp32
__device__ int   d_cnt[MAXN];
__device__ int   d_fill[MAXN];
__device__ int   d_off[MAXN + 1];
__device__ float d_dinv[MAXN];
__device__ int2  d_csr[MAXE];
__device__ int   d_bsum[128];
__device__ float d_stats[256];      // two buffers of 128: [sum64|sumsq64] x2

// ---------------- CSR construction ----------------
__global__ void zero_kernel(int N) {
    int i = blockIdx.x * blockDim.x + threadIdx.x;
    if (i < N) d_cnt[i] = 0;
}

__global__ void hist_kernel(const int* __restrict__ dst, int E) {
    int i = blockIdx.x * blockDim.x + threadIdx.x;
    if (i < E) atomicAdd(&d_cnt[dst[i]], 1);
}

// per-1024-chunk sums + fused dinv
__global__ void scanA_kernel(int N) {
    __shared__ int sh[256];
    int base = blockIdx.x * 1024 + threadIdx.x * 4;
    int t = 0;
#pragma unroll
    for (int j = 0; j < 4; j++) {
        int i = base + j;
        if (i < N) {
            int c = d_cnt[i];
            t += c;
            d_dinv[i] = rsqrtf((float)(c + 1));   // +1 self loop
        }
    }
    sh[threadIdx.x] = t;
    __syncthreads();
    for (int o = 128; o > 0; o >>= 1) {
        if (threadIdx.x < o) sh[threadIdx.x] += sh[threadIdx.x + o];
        __syncthreads();
    }
    if (threadIdx.x == 0) d_bsum[blockIdx.x] = sh[0];
}

// local exclusive scan; block prefix recomputed locally from d_bsum (no scanB);
// also zeroes d_fill; last block writes d_off[N]
__global__ void scanC_kernel(int G, int N) {
    __shared__ int sh[256];
    __shared__ int bs[128];
    __shared__ int bprefix;
    int tid = threadIdx.x;
    if (tid < G) bs[tid] = d_bsum[tid];
    __syncthreads();
    if (tid == 0) {
        int p = 0;
        for (int b = 0; b < (int)blockIdx.x; b++) p += bs[b];
        bprefix = p;
    }
    int base = blockIdx.x * 1024 + tid * 4;
    int v[4]; int t = 0;
#pragma unroll
    for (int j = 0; j < 4; j++) { v[j] = (base + j < N) ? d_cnt[base + j] : 0; t += v[j]; }
    sh[tid] = t;
    __syncthreads();
    for (int o = 1; o < 256; o <<= 1) {
        int x = (tid >= o) ? sh[tid - o] : 0;
        __syncthreads();
        sh[tid] += x;
        __syncthreads();
    }
    int excl = sh[tid] - t + bprefix;
#pragma unroll
    for (int j = 0; j < 4; j++) {
        if (base + j < N) { d_off[base + j] = excl; d_fill[base + j] = 0; excl += v[j]; }
    }
    if ((int)blockIdx.x == G - 1 && tid == 255) d_off[N] = bprefix + sh[255];
}

__global__ void scatter_kernel(const int* __restrict__ src,
                               const int* __restrict__ dst, int E) {
    int i = blockIdx.x * blockDim.x + threadIdx.x;
    if (i >= E) return;
    int s = src[i];
    int d = dst[i];
    int pos = d_off[d] + atomicAdd(&d_fill[d], 1);
    float w = d_dinv[s] * d_dinv[d];
    d_csr[pos] = make_int2(s, __float_as_int(w));
}

// ---------------- GEMM: 128-row tile, 8x(NC/8) thread tile, transposed-X smem ----------------
// A[M,K] @ W[K,NC]. BNIN: normalize+relu A via d_stats[bnoff]+g/bt.
// zsoff>=0: block 0 zeroes d_stats[zsoff..+127].
// DOT: fused bias+relu+dot epilogue -> out[M].  !DOT: writes d_hw as fp16 rows.
template <int K, int NC, bool USE_X, bool BNIN, bool DOT>
__global__ void gemm_kernel(const float* __restrict__ A_ext, const float* __restrict__ Wm,
                            const float* __restrict__ g, const float* __restrict__ bt,
                            const float* __restrict__ lb1, const float* __restrict__ lw2,
                            const float* __restrict__ lb2, float* __restrict__ out,
                            int M, int bnoff, int zsoff) {
    constexpr int CH = 32;
    constexpr int NCc = NC / 8;       // 8 or 4 cols per thread
    __shared__ __align__(16) float Xs[CH][128];
    __shared__ __align__(16) float Ws[CH][NC];
    __shared__ float s_sc[64], s_sh[64];

    int tid = threadIdx.x;            // 128 threads
    if (zsoff >= 0 && blockIdx.x == 0) d_stats[zsoff + tid] = 0.f;

    if (BNIN && tid < 64) {
        float invM = 1.f / (float)M;
        float mu  = d_stats[bnoff + tid] * invM;
        float var = d_stats[bnoff + 64 + tid] * invM - mu * mu;
        float sc  = rsqrtf(var + 1e-5f) * g[tid];
        s_sc[tid] = sc;
        s_sh[tid] = bt[tid] - mu * sc;
    }
    if (BNIN) __syncthreads();

    const float* A = USE_X ? A_ext : d_hbuf;
    int m0 = blockIdx.x * 128;
    int row = m0 + tid;
    bool rv = row < M;
    int tx = tid % 8;
    int ty = tid / 8;
    float acc[8][NCc] = {};

    for (int kc = 0; kc < K; kc += CH) {
#pragma unroll
        for (int i = tid; i < CH * NC / 4; i += 128)
            ((float4*)Ws)[i] = ((const float4*)(Wm + (size_t)kc * NC))[i];
#pragma unroll
        for (int k4 = 0; k4 < CH / 4; k4++) {
            float4 a = rv ? *(const float4*)(A + (size_t)row * K + kc + k4 * 4)
                          : make_float4(0.f, 0.f, 0.f, 0.f);
            if (BNIN) {
                int c = kc + k4 * 4;
                a.x = fmaxf(fmaf(a.x, s_sc[c + 0], s_sh[c + 0]), 0.f);
                a.y = fmaxf(fmaf(a.y, s_sc[c + 1], s_sh[c + 1]), 0.f);
                a.z = fmaxf(fmaf(a.z, s_sc[c + 2], s_sh[c + 2]), 0.f);
                a.w = fmaxf(fmaf(a.w, s_sc[c + 3], s_sh[c + 3]), 0.f);
            }
            Xs[k4 * 4 + 0][tid] = a.x;
            Xs[k4 * 4 + 1][tid] = a.y;
            Xs[k4 * 4 + 2][tid] = a.z;
            Xs[k4 * 4 + 3][tid] = a.w;
        }
        __syncthreads();
#pragma unroll 8
        for (int k = 0; k < CH; k++) {
            float xv[8];
            *(float4*)&xv[0] = *(const float4*)&Xs[k][ty * 8];
            *(float4*)&xv[4] = *(const float4*)&Xs[k][ty * 8 + 4];
            float wv[NCc];
            *(float4*)&wv[0] = *(const float4*)&Ws[k][tx * NCc];
            if (NCc == 8)
                *(float4*)&wv[4] = *(const float4*)&Ws[k][tx * NCc + 4];
#pragma unroll
            for (int i = 0; i < 8; i++)
#pragma unroll
                for (int j = 0; j < NCc; j++)
                    acc[i][j] = fmaf(xv[i], wv[j], acc[i][j]);
        }
        __syncthreads();
    }

    if (!DOT) {
        // write fp16 rows: 8 cols per thread = 4 half2 = one 16B store
        __half2* hwh = (__half2*)d_hw;
#pragma unroll
        for (int i = 0; i < 8; i++) {
            int r = m0 + ty * 8 + i;
            if (r < M) {
                __half2 p0 = __floats2half2_rn(acc[i][0], acc[i][1]);
                __half2 p1 = __floats2half2_rn(acc[i][2], acc[i][3]);
                __half2 p2 = __floats2half2_rn(acc[i][4], acc[i][5]);
                __half2 p3 = __floats2half2_rn(acc[i][6], acc[i][7]);
                uint4 u;
                u.x = *(unsigned*)&p0;
                u.y = *(unsigned*)&p1;
                u.z = *(unsigned*)&p2;
                u.w = *(unsigned*)&p3;
                *(uint4*)(hwh + (size_t)r * 32 + tx * 4) = u;
            }
        }
    } else {
        int c0 = tx * NCc;   // NCc==4
        float lb[4], lw[4];
#pragma unroll
        for (int j = 0; j < 4; j++) { lb[j] = lb1[c0 + j]; lw[j] = lw2[c0 + j]; }
        float lbias = lb2[0];
#pragma unroll
        for (int i = 0; i < 8; i++) {
            float p = 0.f;
#pragma unroll
            for (int j = 0; j < 4; j++)
                p = fmaf(fmaxf(acc[i][j] + lb[j], 0.f), lw[j], p);
            p += __shfl_down_sync(0xffffffffu, p, 4, 8);
            p += __shfl_down_sync(0xffffffffu, p, 2, 8);
            p += __shfl_down_sync(0xffffffffu, p, 1, 8);
            if (tx == 0) {
                int r = m0 + ty * 8 + i;
                if (r < M) out[r] = p + lbias;
            }
        }
    }
}

// ---------------- aggregation: warp per node, fp16 gather, unroll-4 + fused BN stats ----------------
__global__ void __launch_bounds__(512, 3) agg_kernel(int N, int sb) {
    __shared__ float s_sum[16][65];
    __shared__ float s_sq[16][65];
    const __half2* hw2 = (const __half2*)d_hw;
    float2* out2 = (float2*)d_hbuf;
    int warp = threadIdx.x >> 5;
    int lane = threadIdx.x & 31;
    int node = blockIdx.x * 16 + warp;
    float2 acc = make_float2(0.f, 0.f);
    if (node < N) {
        float dv = d_dinv[node];
        float sw = dv * dv;
        float2 v0 = __half22float2(hw2[(size_t)node * 32 + lane]);
        acc.x = v0.x * sw;
        acc.y = v0.y * sw;
        int s = d_off[node], e = d_off[node + 1];
        int i = s;
        int e4 = s + ((e - s) & ~3);
        for (; i < e4; i += 4) {
            int2 c0 = d_csr[i];
            int2 c1 = d_csr[i + 1];
            int2 c2 = d_csr[i + 2];
            int2 c3 = d_csr[i + 3];
            float2 v0_ = __half22float2(hw2[(size_t)c0.x * 32 + lane]);
            float2 v1_ = __half22float2(hw2[(size_t)c1.x * 32 + lane]);
            float2 v2_ = __half22float2(hw2[(size_t)c2.x * 32 + lane]);
            float2 v3_ = __half22float2(hw2[(size_t)c3.x * 32 + lane]);
            acc.x = fmaf(__int_as_float(c0.y), v0_.x, acc.x);
            acc.y = fmaf(__int_as_float(c0.y), v0_.y, acc.y);
            acc.x = fmaf(__int_as_float(c1.y), v1_.x, acc.x);
            acc.y = fmaf(__int_as_float(c1.y), v1_.y, acc.y);
            acc.x = fmaf(__int_as_float(c2.y), v2_.x, acc.x);
            acc.y = fmaf(__int_as_float(c2.y), v2_.y, acc.y);
            acc.x = fmaf(__int_as_float(c3.y), v3_.x, acc.x);
            acc.y = fmaf(__int_as_float(c3.y), v3_.y, acc.y);
        }
        for (; i < e; i++) {
            int2 ed = d_csr[i];
            float w = __int_as_float(ed.y);
            float2 v = __half22float2(hw2[(size_t)ed.x * 32 + lane]);
            acc.x = fmaf(w, v.x, acc.x);
            acc.y = fmaf(w, v.y, acc.y);
        }
        out2[(size_t)node * 32 + lane] = acc;
    }
    s_sum[warp][2 * lane]     = acc.x;
    s_sum[warp][2 * lane + 1] = acc.y;
    s_sq[warp][2 * lane]      = acc.x * acc.x;
    s_sq[warp][2 * lane + 1]  = acc.y * acc.y;
    __syncthreads();
    if (threadIdx.x < 64) {
        int c = threadIdx.x;
        float t = 0.f, q = 0.f;
#pragma unroll
        for (int w = 0; w < 16; w++) { t += s_sum[w][c]; q += s_sq[w][c]; }
        atomicAdd(&d_stats[sb + c], t);
        atomicAdd(&d_stats[sb + 64 + c], q);
    }
}

// ---------------- host orchestration (kernel launches ONLY) ----------------
extern "C" void kernel_launch(void* const* d_in, const int* in_sizes, int n_in,
                              void* d_out, int out_size) {
    const float* x   = (const float*)d_in[0];
    const int*   ei  = (const int*)d_in[1];
    const float* W0  = (const float*)d_in[2];
    const float* g0  = (const float*)d_in[4];
    const float* bt0 = (const float*)d_in[5];
    const float* W1  = (const float*)d_in[6];
    const float* g1  = (const float*)d_in[8];
    const float* bt1 = (const float*)d_in[9];
    const float* W2  = (const float*)d_in[10];
    const float* g2  = (const float*)d_in[12];
    const float* bt2 = (const float*)d_in[13];
    const float* lw1 = (const float*)d_in[14];
    const float* lb1 = (const float*)d_in[15];
    const float* lw2 = (const float*)d_in[16];
    const float* lb2 = (const float*)d_in[17];
    float* out = (float*)d_out;

    int N = out_size;
    int E = in_sizes[1] / 2;
    if (N > MAXN || E > MAXE) return;

    const int* src = ei;
    const int* dst = ei + E;

    int bN = (N + 255) / 256;
    int bE = (E + 255) / 256;
    int G  = (N + 1023) / 1024;
    int gB   = (N + 127) / 128;
    int aggB = (N + 15) / 16;

    // CSR build interleaved with the independent layer-0 GEMM
    zero_kernel<<<bN, 256>>>(N);
    hist_kernel<<<bE, 256>>>(dst, E);
    scanA_kernel<<<G, 256>>>(N);
    // slot 4: layer-0 GEMM (independent of CSR) -> profiled launch
    gemm_kernel<128, 64, true, false, false><<<gB, 128>>>(
        x, W0, nullptr, nullptr, nullptr, nullptr, nullptr, nullptr, N, 0, 0);
    scanC_kernel<<<G, 256>>>(G, N);
    scatter_kernel<<<bE, 256>>>(src, dst, E);

    // L0 agg -> hbuf + stats buf0
    agg_kernel<<<aggB, 512>>>(N, 0);

    // L1: BN0(hbuf) @ W1 -> hw fp16 (zero buf1); agg -> stats buf1
    gemm_kernel<64, 64, false, true, false><<<gB, 128>>>(
        nullptr, W1, g0, bt0, nullptr, nullptr, nullptr, nullptr, N, 0, 128);
    agg_kernel<<<aggB, 512>>>(N, 128);

    // L2: BN1(hbuf) @ W2 -> hw fp16 (zero buf0); agg -> stats buf0
    gemm_kernel<64, 64, false, true, false><<<gB, 128>>>(
        nullptr, W2, g1, bt1, nullptr, nullptr, nullptr, nullptr, N, 128, 0);
    agg_kernel<<<aggB, 512>>>(N, 0);

    // MLP head fused: relu(BN2(hbuf) @ lw1 + lb1) . lw2 + lb2 -> out
    gemm_kernel<64, 32, false, true, true><<<gB, 128>>>(
        nullptr, lw1, g2, bt2, lb1, lw2, lb2, out, N, 0, -1);
}

// round 6
// speedup vs baseline: 1.2337x; 1.0710x over previous
#include <cuda_runtime.h>
#include <cuda_fp16.h>

#define MAXN 100000
#define MAXE 1600000
#define HIDF 64

// packed fp32x2 FMA (SASS FFMA2) — only reachable via PTX
#define FMA_F32X2(d, a, b) asm("fma.rn.f32x2 %0, %1, %2, %0;" : "+l"(d) : "l"(a), "l"(b))
#define PACK_DUP_F32X2(out, x) asm("mov.b64 %0, {%1, %1};" : "=l"(out) : "r"(__float_as_uint(x)))
#define UNPACK_F32X2_(lo, hi, in) asm("mov.b64 {%0, %1}, %2;" : "=f"(lo), "=f"(hi) : "l"(in))

// ---------------- static device scratch ----------------
__device__ __align__(16) float d_hw[(size_t)MAXN * HIDF];    // holds fp16 rows (N x 64 halves)
__device__ __align__(16) float d_hbuf[(size_t)MAXN * HIDF];  // aggregated features fp32
__device__ int   d_cnt[MAXN];
__device__ int   d_fill[MAXN];
__device__ int   d_off[MAXN + 1];
__device__ float d_dinv[MAXN];
__device__ int2  d_csr[MAXE];
__device__ int   d_bsum[128];
__device__ float d_stats[256];      // two buffers of 128: [sum64|sumsq64] x2

// ---------------- CSR construction ----------------
__global__ void zero_kernel(int N) {
    int i = blockIdx.x * blockDim.x + threadIdx.x;
    if (i < N) d_cnt[i] = 0;
}

__global__ void hist_kernel(const int* __restrict__ dst, int E) {
    int i = blockIdx.x * blockDim.x + threadIdx.x;
    if (i < E) atomicAdd(&d_cnt[dst[i]], 1);
}

__global__ void scanA_kernel(int N) {
    __shared__ int sh[256];
    int base = blockIdx.x * 1024 + threadIdx.x * 4;
    int t = 0;
#pragma unroll
    for (int j = 0; j < 4; j++) {
        int i = base + j;
        if (i < N) {
            int c = d_cnt[i];
            t += c;
            d_dinv[i] = rsqrtf((float)(c + 1));
        }
    }
    sh[threadIdx.x] = t;
    __syncthreads();
    for (int o = 128; o > 0; o >>= 1) {
        if (threadIdx.x < o) sh[threadIdx.x] += sh[threadIdx.x + o];
        __syncthreads();
    }
    if (threadIdx.x == 0) d_bsum[blockIdx.x] = sh[0];
}

__global__ void scanC_kernel(int G, int N) {
    __shared__ int sh[256];
    __shared__ int bs[128];
    __shared__ int bprefix;
    int tid = threadIdx.x;
    if (tid < G) bs[tid] = d_bsum[tid];
    __syncthreads();
    if (tid == 0) {
        int p = 0;
        for (int b = 0; b < (int)blockIdx.x; b++) p += bs[b];
        bprefix = p;
    }
    int base = blockIdx.x * 1024 + tid * 4;
    int v[4]; int t = 0;
#pragma unroll
    for (int j = 0; j < 4; j++) { v[j] = (base + j < N) ? d_cnt[base + j] : 0; t += v[j]; }
    sh[tid] = t;
    __syncthreads();
    for (int o = 1; o < 256; o <<= 1) {
        int x = (tid >= o) ? sh[tid - o] : 0;
        __syncthreads();
        sh[tid] += x;
        __syncthreads();
    }
    int excl = sh[tid] - t + bprefix;
#pragma unroll
    for (int j = 0; j < 4; j++) {
        if (base + j < N) { d_off[base + j] = excl; d_fill[base + j] = 0; excl += v[j]; }
    }
    if ((int)blockIdx.x == G - 1 && tid == 255) d_off[N] = bprefix + sh[255];
}

__global__ void scatter_kernel(const int* __restrict__ src,
                               const int* __restrict__ dst, int E) {
    int i = blockIdx.x * blockDim.x + threadIdx.x;
    if (i >= E) return;
    int s = src[i];
    int d = dst[i];
    int pos = d_off[d] + atomicAdd(&d_fill[d], 1);
    float w = d_dinv[s] * d_dinv[d];
    d_csr[pos] = make_int2(s, __float_as_int(w));
}

// ---------------- GEMM with FFMA2 inner loop ----------------
// A[M,K] @ W[K,NC]. BNIN: normalize+relu A via d_stats[bnoff]+g/bt.
// zsoff>=0: block 0 zeroes d_stats[zsoff..+127].
// DOT: fused bias+relu+dot epilogue -> out[M].  !DOT: writes d_hw as fp16 rows.
template <int K, int NC, bool USE_X, bool BNIN, bool DOT>
__global__ void gemm_kernel(const float* __restrict__ A_ext, const float* __restrict__ Wm,
                            const float* __restrict__ g, const float* __restrict__ bt,
                            const float* __restrict__ lb1, const float* __restrict__ lw2,
                            const float* __restrict__ lb2, float* __restrict__ out,
                            int M, int bnoff, int zsoff) {
    constexpr int CH = 32;
    constexpr int NCc = NC / 8;       // 8 or 4 cols per thread
    constexpr int NP = NCc / 2;       // packed pairs per thread (4 or 2)
    __shared__ __align__(16) float Xs[CH][128];
    __shared__ __align__(16) float Ws[CH][NC];
    __shared__ float s_sc[64], s_sh[64];

    int tid = threadIdx.x;            // 128 threads
    if (zsoff >= 0 && blockIdx.x == 0) d_stats[zsoff + tid] = 0.f;

    if (BNIN && tid < 64) {
        float invM = 1.f / (float)M;
        float mu  = d_stats[bnoff + tid] * invM;
        float var = d_stats[bnoff + 64 + tid] * invM - mu * mu;
        float sc  = rsqrtf(var + 1e-5f) * g[tid];
        s_sc[tid] = sc;
        s_sh[tid] = bt[tid] - mu * sc;
    }
    if (BNIN) __syncthreads();

    const float* A = USE_X ? A_ext : d_hbuf;
    int m0 = blockIdx.x * 128;
    int row = m0 + tid;
    bool rv = row < M;
    int tx = tid % 8;
    int ty = tid / 8;
    unsigned long long acc2[8][NP] = {};

    for (int kc = 0; kc < K; kc += CH) {
#pragma unroll
        for (int i = tid; i < CH * NC / 4; i += 128)
            ((float4*)Ws)[i] = ((const float4*)(Wm + (size_t)kc * NC))[i];
#pragma unroll
        for (int k4 = 0; k4 < CH / 4; k4++) {
            float4 a = rv ? *(const float4*)(A + (size_t)row * K + kc + k4 * 4)
                          : make_float4(0.f, 0.f, 0.f, 0.f);
            if (BNIN) {
                int c = kc + k4 * 4;
                a.x = fmaxf(fmaf(a.x, s_sc[c + 0], s_sh[c + 0]), 0.f);
                a.y = fmaxf(fmaf(a.y, s_sc[c + 1], s_sh[c + 1]), 0.f);
                a.z = fmaxf(fmaf(a.z, s_sc[c + 2], s_sh[c + 2]), 0.f);
                a.w = fmaxf(fmaf(a.w, s_sc[c + 3], s_sh[c + 3]), 0.f);
            }
            Xs[k4 * 4 + 0][tid] = a.x;
            Xs[k4 * 4 + 1][tid] = a.y;
            Xs[k4 * 4 + 2][tid] = a.z;
            Xs[k4 * 4 + 3][tid] = a.w;
        }
        __syncthreads();
#pragma unroll 8
        for (int k = 0; k < CH; k++) {
            float xv[8];
            *(float4*)&xv[0] = *(const float4*)&Xs[k][ty * 8];
            *(float4*)&xv[4] = *(const float4*)&Xs[k][ty * 8 + 4];
            unsigned long long wp[NP];
            *(ulonglong2*)&wp[0] = *(const ulonglong2*)&Ws[k][tx * NCc];
            if (NP == 4)
                *(ulonglong2*)&wp[2] = *(const ulonglong2*)&Ws[k][tx * NCc + 4];
#pragma unroll
            for (int i = 0; i < 8; i++) {
                unsigned long long xp;
                PACK_DUP_F32X2(xp, xv[i]);
#pragma unroll
                for (int j = 0; j < NP; j++)
                    FMA_F32X2(acc2[i][j], xp, wp[j]);
            }
        }
        __syncthreads();
    }

    if (!DOT) {
        __half2* hwh = (__half2*)d_hw;
#pragma unroll
        for (int i = 0; i < 8; i++) {
            int r = m0 + ty * 8 + i;
            if (r < M) {
                float a0, a1, a2, a3, a4, a5, a6, a7;
                UNPACK_F32X2_(a0, a1, acc2[i][0]);
                UNPACK_F32X2_(a2, a3, acc2[i][1]);
                UNPACK_F32X2_(a4, a5, acc2[i][2]);
                UNPACK_F32X2_(a6, a7, acc2[i][3]);
                __half2 p0 = __floats2half2_rn(a0, a1);
                __half2 p1 = __floats2half2_rn(a2, a3);
                __half2 p2 = __floats2half2_rn(a4, a5);
                __half2 p3 = __floats2half2_rn(a6, a7);
                uint4 u;
                u.x = *(unsigned*)&p0;
                u.y = *(unsigned*)&p1;
                u.z = *(unsigned*)&p2;
                u.w = *(unsigned*)&p3;
                *(uint4*)(hwh + (size_t)r * 32 + tx * 4) = u;
            }
        }
    } else {
        int c0 = tx * NCc;   // NCc==4
        float lb[4], lw[4];
#pragma unroll
        for (int j = 0; j < 4; j++) { lb[j] = lb1[c0 + j]; lw[j] = lw2[c0 + j]; }
        float lbias = lb2[0];
#pragma unroll
        for (int i = 0; i < 8; i++) {
            float a0, a1, a2, a3;
            UNPACK_F32X2_(a0, a1, acc2[i][0]);
            UNPACK_F32X2_(a2, a3, acc2[i][1]);
            float p = 0.f;
            p = fmaf(fmaxf(a0 + lb[0], 0.f), lw[0], p);
            p = fmaf(fmaxf(a1 + lb[1], 0.f), lw[1], p);
            p = fmaf(fmaxf(a2 + lb[2], 0.f), lw[2], p);
            p = fmaf(fmaxf(a3 + lb[3], 0.f), lw[3], p);
            p += __shfl_down_sync(0xffffffffu, p, 4, 8);
            p += __shfl_down_sync(0xffffffffu, p, 2, 8);
            p += __shfl_down_sync(0xffffffffu, p, 1, 8);
            if (tx == 0) {
                int r = m0 + ty * 8 + i;
                if (r < M) out[r] = p + lbias;
            }
        }
    }
}

// ---------------- aggregation: warp per node, fp16 gather, unroll-4 + fused BN stats ----------------
__global__ void __launch_bounds__(512, 3) agg_kernel(int N, int sb) {
    __shared__ float s_sum[16][65];
    __shared__ float s_sq[16][65];
    const __half2* hw2 = (const __half2*)d_hw;
    float2* out2 = (float2*)d_hbuf;
    int warp = threadIdx.x >> 5;
    int lane = threadIdx.x & 31;
    int node = blockIdx.x * 16 + warp;
    float2 acc = make_float2(0.f, 0.f);
    if (node < N) {
        float dv = d_dinv[node];
        float sw = dv * dv;
        float2 v0 = __half22float2(hw2[(size_t)node * 32 + lane]);
        acc.x = v0.x * sw;
        acc.y = v0.y * sw;
        int s = d_off[node], e = d_off[node + 1];
        int i = s;
        int e4 = s + ((e - s) & ~3);
        for (; i < e4; i += 4) {
            int2 c0 = d_csr[i];
            int2 c1 = d_csr[i + 1];
            int2 c2 = d_csr[i + 2];
            int2 c3 = d_csr[i + 3];
            float2 v0_ = __half22float2(hw2[(size_t)c0.x * 32 + lane]);
            float2 v1_ = __half22float2(hw2[(size_t)c1.x * 32 + lane]);
            float2 v2_ = __half22float2(hw2[(size_t)c2.x * 32 + lane]);
            float2 v3_ = __half22float2(hw2[(size_t)c3.x * 32 + lane]);
            acc.x = fmaf(__int_as_float(c0.y), v0_.x, acc.x);
            acc.y = fmaf(__int_as_float(c0.y), v0_.y, acc.y);
            acc.x = fmaf(__int_as_float(c1.y), v1_.x, acc.x);
            acc.y = fmaf(__int_as_float(c1.y), v1_.y, acc.y);
            acc.x = fmaf(__int_as_float(c2.y), v2_.x, acc.x);
            acc.y = fmaf(__int_as_float(c2.y), v2_.y, acc.y);
            acc.x = fmaf(__int_as_float(c3.y), v3_.x, acc.x);
            acc.y = fmaf(__int_as_float(c3.y), v3_.y, acc.y);
        }
        for (; i < e; i++) {
            int2 ed = d_csr[i];
            float w = __int_as_float(ed.y);
            float2 v = __half22float2(hw2[(size_t)ed.x * 32 + lane]);
            acc.x = fmaf(w, v.x, acc.x);
            acc.y = fmaf(w, v.y, acc.y);
        }
        out2[(size_t)node * 32 + lane] = acc;
    }
    s_sum[warp][2 * lane]     = acc.x;
    s_sum[warp][2 * lane + 1] = acc.y;
    s_sq[warp][2 * lane]      = acc.x * acc.x;
    s_sq[warp][2 * lane + 1]  = acc.y * acc.y;
    __syncthreads();
    if (threadIdx.x < 64) {
        int c = threadIdx.x;
        float t = 0.f, q = 0.f;
#pragma unroll
        for (int w = 0; w < 16; w++) { t += s_sum[w][c]; q += s_sq[w][c]; }
        atomicAdd(&d_stats[sb + c], t);
        atomicAdd(&d_stats[sb + 64 + c], q);
    }
}

// ---------------- host orchestration (kernel launches ONLY) ----------------
extern "C" void kernel_launch(void* const* d_in, const int* in_sizes, int n_in,
                              void* d_out, int out_size) {
    const float* x   = (const float*)d_in[0];
    const int*   ei  = (const int*)d_in[1];
    const float* W0  = (const float*)d_in[2];
    const float* g0  = (const float*)d_in[4];
    const float* bt0 = (const float*)d_in[5];
    const float* W1  = (const float*)d_in[6];
    const float* g1  = (const float*)d_in[8];
    const float* bt1 = (const float*)d_in[9];
    const float* W2  = (const float*)d_in[10];
    const float* g2  = (const float*)d_in[12];
    const float* bt2 = (const float*)d_in[13];
    const float* lw1 = (const float*)d_in[14];
    const float* lb1 = (const float*)d_in[15];
    const float* lw2 = (const float*)d_in[16];
    const float* lb2 = (const float*)d_in[17];
    float* out = (float*)d_out;

    int N = out_size;
    int E = in_sizes[1] / 2;
    if (N > MAXN || E > MAXE) return;

    const int* src = ei;
    const int* dst = ei + E;

    int bN = (N + 255) / 256;
    int bE = (E + 255) / 256;
    int G  = (N + 1023) / 1024;
    int gB   = (N + 127) / 128;
    int aggB = (N + 15) / 16;

    // CSR build interleaved with the independent layer-0 GEMM
    zero_kernel<<<bN, 256>>>(N);
    hist_kernel<<<bE, 256>>>(dst, E);
    scanA_kernel<<<G, 256>>>(N);
    // profiled slot: layer-0 GEMM (independent of CSR)
    gemm_kernel<128, 64, true, false, false><<<gB, 128>>>(
        x, W0, nullptr, nullptr, nullptr, nullptr, nullptr, nullptr, N, 0, 0);
    scanC_kernel<<<G, 256>>>(G, N);
    scatter_kernel<<<bE, 256>>>(src, dst, E);

    // L0 agg -> hbuf + stats buf0
    agg_kernel<<<aggB, 512>>>(N, 0);

    // L1: BN0(hbuf) @ W1 -> hw fp16 (zero buf1); agg -> stats buf1
    gemm_kernel<64, 64, false, true, false><<<gB, 128>>>(
        nullptr, W1, g0, bt0, nullptr, nullptr, nullptr, nullptr, N, 0, 128);
    agg_kernel<<<aggB, 512>>>(N, 128);

    // L2: BN1(hbuf) @ W2 -> hw fp16 (zero buf0); agg -> stats buf0
    gemm_kernel<64, 64, false, true, false><<<gB, 128>>>(
        nullptr, W2, g1, bt1, nullptr, nullptr, nullptr, nullptr, N, 128, 0);
    agg_kernel<<<aggB, 512>>>(N, 0);

    // MLP head fused: relu(BN2(hbuf) @ lw1 + lb1) . lw2 + lb2 -> out
    gemm_kernel<64, 32, false, true, true><<<gB, 128>>>(
        nullptr, lw1, g2, bt2, lb1, lw2, lb2, out, N, 0, -1);
}

// round 8
// speedup vs baseline: 1.5247x; 1.2359x over previous
#include <cuda_runtime.h>
#include <cuda_fp16.h>
#include <mma.h>
using namespace nvcuda;

#define MAXN 100000
#define MAXE 1600000
#define HIDF 64

// ---------------- static device scratch ----------------
__device__ __align__(16) float d_hw[(size_t)MAXN * HIDF];    // fp16 rows (N x 64 halves)
__device__ __align__(16) float d_hbuf[(size_t)MAXN * HIDF];  // aggregated features fp32
__device__ int   d_cnt[MAXN];
__device__ int   d_fill[MAXN];
__device__ int   d_off[MAXN + 1];
__device__ float d_dinv[MAXN];
__device__ int2  d_csr[MAXE];
__device__ int   d_bsum[128];
__device__ float d_stats[256];      // two buffers of 128: [sum64|sumsq64] x2

// ---------------- CSR construction ----------------
__global__ void zero_kernel(int N) {
    int i = blockIdx.x * blockDim.x + threadIdx.x;
    if (i < N) d_cnt[i] = 0;
}

__global__ void hist_kernel(const int* __restrict__ dst, int E) {
    int i = blockIdx.x * blockDim.x + threadIdx.x;
    if (i < E) atomicAdd(&d_cnt[dst[i]], 1);
}

__global__ void scanA_kernel(int N) {
    __shared__ int sh[256];
    int base = blockIdx.x * 1024 + threadIdx.x * 4;
    int t = 0;
#pragma unroll
    for (int j = 0; j < 4; j++) {
        int i = base + j;
        if (i < N) {
            int c = d_cnt[i];
            t += c;
            d_dinv[i] = rsqrtf((float)(c + 1));
        }
    }
    sh[threadIdx.x] = t;
    __syncthreads();
    for (int o = 128; o > 0; o >>= 1) {
        if (threadIdx.x < o) sh[threadIdx.x] += sh[threadIdx.x + o];
        __syncthreads();
    }
    if (threadIdx.x == 0) d_bsum[blockIdx.x] = sh[0];
}

__global__ void scanC_kernel(int G, int N) {
    __shared__ int sh[256];
    __shared__ int bs[128];
    __shared__ int bprefix;
    int tid = threadIdx.x;
    if (tid < G) bs[tid] = d_bsum[tid];
    __syncthreads();
    if (tid == 0) {
        int p = 0;
        for (int b = 0; b < (int)blockIdx.x; b++) p += bs[b];
        bprefix = p;
    }
    int base = blockIdx.x * 1024 + tid * 4;
    int v[4]; int t = 0;
#pragma unroll
    for (int j = 0; j < 4; j++) { v[j] = (base + j < N) ? d_cnt[base + j] : 0; t += v[j]; }
    sh[tid] = t;
    __syncthreads();
    for (int o = 1; o < 256; o <<= 1) {
        int x = (tid >= o) ? sh[tid - o] : 0;
        __syncthreads();
        sh[tid] += x;
        __syncthreads();
    }
    int excl = sh[tid] - t + bprefix;
#pragma unroll
    for (int j = 0; j < 4; j++) {
        if (base + j < N) { d_off[base + j] = excl; d_fill[base + j] = 0; excl += v[j]; }
    }
    if ((int)blockIdx.x == G - 1 && tid == 255) d_off[N] = bprefix + sh[255];
}

__global__ void scatter_kernel(const int* __restrict__ src,
                               const int* __restrict__ dst, int E) {
    int i = blockIdx.x * blockDim.x + threadIdx.x;
    if (i >= E) return;
    int s = src[i];
    int d = dst[i];
    int pos = d_off[d] + atomicAdd(&d_fill[d], 1);
    float w = d_dinv[s] * d_dinv[d];
    d_csr[pos] = make_int2(s, __float_as_int(w));
}

__device__ __forceinline__ void split_h2(float a, float b, half2& hi, half2& lo) {
    half2 h = __floats2half2_rn(a, b);
    float2 hf = __half22float2(h);
    hi = h;
    lo = __floats2half2_rn(a - hf.x, b - hf.y);
}

// ---------------- split-fp16 wmma GEMM: effectively fp32-accurate on tensor cores ----------------
// A[M,K] @ W[K,NC]. 128 threads = 4 warps, 64 rows/block, K chunked by 32.
// A = Ah+Al, W = Wh+Wl (fp16 splits); acc += Ah*Wh + Ah*Wl + Al*Wh  (fp32 accum).
// BNIN: BN+ReLU A in fp32 before splitting. zsoff>=0: block 0 zeroes d_stats[zsoff..+127].
// DOT: fused bias+relu+dot epilogue -> out[M]. !DOT: d_hw fp16 rows.
template <int K, int NC, bool USE_X, bool BNIN, bool DOT>
__global__ void __launch_bounds__(128) gemm_kernel(
        const float* __restrict__ A_ext, const float* __restrict__ Wm,
        const float* __restrict__ g, const float* __restrict__ bt,
        const float* __restrict__ lb1, const float* __restrict__ lw2,
        const float* __restrict__ lb2, float* __restrict__ out,
        int M, int bnoff, int zsoff) {
    constexpr int CH  = 32;
    constexpr int LDA = CH + 8;   // halves
    constexpr int LDB = NC + 8;   // halves
    constexpr int LDC = NC + 4;   // floats
    constexpr int A_HALVES = 64 * LDA;
    constexpr int W_HALVES = CH * LDB;
    constexpr int AB_BYTES = (2 * A_HALVES + 2 * W_HALVES) * 2;
    constexpr int C_BYTES  = 64 * LDC * 4;
    constexpr int SM_BYTES = AB_BYTES > C_BYTES ? AB_BYTES : C_BYTES;
    __shared__ __align__(16) char smem[SM_BYTES];
    __shared__ float s_sc[64], s_sh[64];
    half*  Ah = (half*)smem;
    half*  Al = Ah + A_HALVES;
    half*  Wh = Al + A_HALVES;
    half*  Wl = Wh + W_HALVES;
    float* Cs = (float*)smem;

    int tid = threadIdx.x;        // 128
    int warp = tid >> 5;
    if (zsoff >= 0 && blockIdx.x == 0) d_stats[zsoff + tid] = 0.f;

    if (BNIN && tid < 64) {
        float invM = 1.f / (float)M;
        float mu  = d_stats[bnoff + tid] * invM;
        float var = d_stats[bnoff + 64 + tid] * invM - mu * mu;
        float sc  = rsqrtf(var + 1e-5f) * g[tid];
        s_sc[tid] = sc;
        s_sh[tid] = bt[tid] - mu * sc;
    }
    if (BNIN) __syncthreads();

    const float* A = USE_X ? A_ext : d_hbuf;
    int m0 = blockIdx.x * 64;

    wmma::fragment<wmma::accumulator, 16, 16, 16, float> acc[NC / 16];
#pragma unroll
    for (int j = 0; j < NC / 16; j++) wmma::fill_fragment(acc[j], 0.f);

    for (int kc = 0; kc < K; kc += CH) {
        // ---- W chunk (CH x NC fp32 -> hi/lo fp16) ----
#pragma unroll
        for (int i = tid; i < CH * NC / 4; i += 128) {
            float4 w = ((const float4*)(Wm + (size_t)kc * NC))[i];
            int r = (i * 4) / NC, c = (i * 4) % NC;
            half2 h0, l0, h1, l1;
            split_h2(w.x, w.y, h0, l0);
            split_h2(w.z, w.w, h1, l1);
            *(half2*)(Wh + r * LDB + c)     = h0;
            *(half2*)(Wh + r * LDB + c + 2) = h1;
            *(half2*)(Wl + r * LDB + c)     = l0;
            *(half2*)(Wl + r * LDB + c + 2) = l1;
        }
        // ---- A chunk (64 x CH fp32 -> [BN+ReLU] -> hi/lo fp16) ----
#pragma unroll
        for (int i = tid; i < 64 * CH / 4; i += 128) {
            int r = i / (CH / 4);
            int c = (i % (CH / 4)) * 4;
            int row = m0 + r;
            float4 a = (row < M) ? *(const float4*)(A + (size_t)row * K + kc + c)
                                 : make_float4(0.f, 0.f, 0.f, 0.f);
            if (BNIN) {
                int cc = kc + c;
                a.x = fmaxf(fmaf(a.x, s_sc[cc + 0], s_sh[cc + 0]), 0.f);
                a.y = fmaxf(fmaf(a.y, s_sc[cc + 1], s_sh[cc + 1]), 0.f);
                a.z = fmaxf(fmaf(a.z, s_sc[cc + 2], s_sh[cc + 2]), 0.f);
                a.w = fmaxf(fmaf(a.w, s_sc[cc + 3], s_sh[cc + 3]), 0.f);
            }
            half2 h0, l0, h1, l1;
            split_h2(a.x, a.y, h0, l0);
            split_h2(a.z, a.w, h1, l1);
            *(half2*)(Ah + r * LDA + c)     = h0;
            *(half2*)(Ah + r * LDA + c + 2) = h1;
            *(half2*)(Al + r * LDA + c)     = l0;
            *(half2*)(Al + r * LDA + c + 2) = l1;
        }
        __syncthreads();

#pragma unroll
        for (int k = 0; k < CH; k += 16) {
            wmma::fragment<wmma::matrix_a, 16, 16, 16, half, wmma::row_major> afh, afl;
            wmma::load_matrix_sync(afh, Ah + (warp * 16) * LDA + k, LDA);
            wmma::load_matrix_sync(afl, Al + (warp * 16) * LDA + k, LDA);
#pragma unroll
            for (int j = 0; j < NC / 16; j++) {
                wmma::fragment<wmma::matrix_b, 16, 16, 16, half, wmma::row_major> bfh, bfl;
                wmma::load_matrix_sync(bfh, Wh + k * LDB + j * 16, LDB);
                wmma::load_matrix_sync(bfl, Wl + k * LDB + j * 16, LDB);
                wmma::mma_sync(acc[j], afh, bfh, acc[j]);
                wmma::mma_sync(acc[j], afh, bfl, acc[j]);
                wmma::mma_sync(acc[j], afl, bfh, acc[j]);
            }
        }
        __syncthreads();
    }

    // ---- epilogue via smem C (overlays A/W planes) ----
#pragma unroll
    for (int j = 0; j < NC / 16; j++)
        wmma::store_matrix_sync(Cs + (warp * 16) * LDC + j * 16, acc[j], LDC,
                                wmma::mem_row_major);
    __syncwarp();   // each thread below reads only its own warp's rows

    int r = tid >> 1;             // row r in [0,64); warp ownership: r/16 == tid/32 ✓
    int row = m0 + r;
    if (!DOT) {
        __half2* hwh = (__half2*)d_hw;
        int c0 = (tid & 1) * 32;
        if (row < M) {
#pragma unroll
            for (int j = 0; j < 32; j += 8) {
                float4 v0 = *(float4*)&Cs[r * LDC + c0 + j];
                float4 v1 = *(float4*)&Cs[r * LDC + c0 + j + 4];
                __half2 p0 = __floats2half2_rn(v0.x, v0.y);
                __half2 p1 = __floats2half2_rn(v0.z, v0.w);
                __half2 p2 = __floats2half2_rn(v1.x, v1.y);
                __half2 p3 = __floats2half2_rn(v1.z, v1.w);
                uint4 u;
                u.x = *(unsigned*)&p0;
                u.y = *(unsigned*)&p1;
                u.z = *(unsigned*)&p2;
                u.w = *(unsigned*)&p3;
                *(uint4*)(hwh + (size_t)row * 32 + (c0 + j) / 2) = u;
            }
        }
    } else {
        int c0 = (tid & 1) * 16;  // NC==32: two threads per row
        float p = 0.f;
#pragma unroll
        for (int j = 0; j < 16; j++)
            p = fmaf(fmaxf(Cs[r * LDC + c0 + j] + lb1[c0 + j], 0.f), lw2[c0 + j], p);
        p += __shfl_xor_sync(0xffffffffu, p, 1);
        if ((tid & 1) == 0 && row < M) out[row] = p + lb2[0];
    }
}

// ---------------- aggregation: warp per node, fp16 gather, unroll-4 + fused BN stats ----------------
__global__ void __launch_bounds__(512, 3) agg_kernel(int N, int sb) {
    __shared__ float s_sum[16][65];
    __shared__ float s_sq[16][65];
    const __half2* hw2 = (const __half2*)d_hw;
    float2* out2 = (float2*)d_hbuf;
    int warp = threadIdx.x >> 5;
    int lane = threadIdx.x & 31;
    int node = blockIdx.x * 16 + warp;
    float2 acc = make_float2(0.f, 0.f);
    if (node < N) {
        float dv = d_dinv[node];
        float sw = dv * dv;
        float2 v0 = __half22float2(hw2[(size_t)node * 32 + lane]);
        acc.x = v0.x * sw;
        acc.y = v0.y * sw;
        int s = d_off[node], e = d_off[node + 1];
        int i = s;
        int e4 = s + ((e - s) & ~3);
        for (; i < e4; i += 4) {
            int2 c0 = d_csr[i];
            int2 c1 = d_csr[i + 1];
            int2 c2 = d_csr[i + 2];
            int2 c3 = d_csr[i + 3];
            float2 v0_ = __half22float2(hw2[(size_t)c0.x * 32 + lane]);
            float2 v1_ = __half22float2(hw2[(size_t)c1.x * 32 + lane]);
            float2 v2_ = __half22float2(hw2[(size_t)c2.x * 32 + lane]);
            float2 v3_ = __half22float2(hw2[(size_t)c3.x * 32 + lane]);
            acc.x = fmaf(__int_as_float(c0.y), v0_.x, acc.x);
            acc.y = fmaf(__int_as_float(c0.y), v0_.y, acc.y);
            acc.x = fmaf(__int_as_float(c1.y), v1_.x, acc.x);
            acc.y = fmaf(__int_as_float(c1.y), v1_.y, acc.y);
            acc.x = fmaf(__int_as_float(c2.y), v2_.x, acc.x);
            acc.y = fmaf(__int_as_float(c2.y), v2_.y, acc.y);
            acc.x = fmaf(__int_as_float(c3.y), v3_.x, acc.x);
            acc.y = fmaf(__int_as_float(c3.y), v3_.y, acc.y);
        }
        for (; i < e; i++) {
            int2 ed = d_csr[i];
            float w = __int_as_float(ed.y);
            float2 v = __half22float2(hw2[(size_t)ed.x * 32 + lane]);
            acc.x = fmaf(w, v.x, acc.x);
            acc.y = fmaf(w, v.y, acc.y);
        }
        out2[(size_t)node * 32 + lane] = acc;
    }
    s_sum[warp][2 * lane]     = acc.x;
    s_sum[warp][2 * lane + 1] = acc.y;
    s_sq[warp][2 * lane]      = acc.x * acc.x;
    s_sq[warp][2 * lane + 1]  = acc.y * acc.y;
    __syncthreads();
    if (threadIdx.x < 64) {
        int c = threadIdx.x;
        float t = 0.f, q = 0.f;
#pragma unroll
        for (int w = 0; w < 16; w++) { t += s_sum[w][c]; q += s_sq[w][c]; }
        atomicAdd(&d_stats[sb + c], t);
        atomicAdd(&d_stats[sb + 64 + c], q);
    }
}

// ---------------- host orchestration (kernel launches ONLY) ----------------
extern "C" void kernel_launch(void* const* d_in, const int* in_sizes, int n_in,
                              void* d_out, int out_size) {
    const float* x   = (const float*)d_in[0];
    const int*   ei  = (const int*)d_in[1];
    const float* W0  = (const float*)d_in[2];
    const float* g0  = (const float*)d_in[4];
    const float* bt0 = (const float*)d_in[5];
    const float* W1  = (const float*)d_in[6];
    const float* g1  = (const float*)d_in[8];
    const float* bt1 = (const float*)d_in[9];
    const float* W2  = (const float*)d_in[10];
    const float* g2  = (const float*)d_in[12];
    const float* bt2 = (const float*)d_in[13];
    const float* lw1 = (const float*)d_in[14];
    const float* lb1 = (const float*)d_in[15];
    const float* lw2 = (const float*)d_in[16];
    const float* lb2 = (const float*)d_in[17];
    float* out = (float*)d_out;

    int N = out_size;
    int E = in_sizes[1] / 2;
    if (N > MAXN || E > MAXE) return;

    const int* src = ei;
    const int* dst = ei + E;

    int bN = (N + 255) / 256;
    int bE = (E + 255) / 256;
    int G  = (N + 1023) / 1024;
    int gB   = (N + 63) / 64;
    int aggB = (N + 15) / 16;

    // CSR build interleaved with the independent layer-0 GEMM
    zero_kernel<<<bN, 256>>>(N);
    hist_kernel<<<bE, 256>>>(dst, E);
    scanA_kernel<<<G, 256>>>(N);
    // profiled slot: layer-0 GEMM (independent of CSR)
    gemm_kernel<128, 64, true, false, false><<<gB, 128>>>(
        x, W0, nullptr, nullptr, nullptr, nullptr, nullptr, nullptr, N, 0, 0);
    scanC_kernel<<<G, 256>>>(G, N);
    scatter_kernel<<<bE, 256>>>(src, dst, E);

    // L0 agg -> hbuf + stats buf0
    agg_kernel<<<aggB, 512>>>(N, 0);

    // L1: BN0(hbuf) @ W1 -> hw fp16 (zero buf1); agg -> stats buf1
    gemm_kernel<64, 64, false, true, false><<<gB, 128>>>(
        nullptr, W1, g0, bt0, nullptr, nullptr, nullptr, nullptr, N, 0, 128);
    agg_kernel<<<aggB, 512>>>(N, 128);

    // L2: BN1(hbuf) @ W2 -> hw fp16 (zero buf0); agg -> stats buf0
    gemm_kernel<64, 64, false, true, false><<<gB, 128>>>(
        nullptr, W2, g1, bt1, nullptr, nullptr, nullptr, nullptr, N, 128, 0);
    agg_kernel<<<aggB, 512>>>(N, 0);

    // MLP head fused: relu(BN2(hbuf) @ lw1 + lb1) . lw2 + lb2 -> out
    gemm_kernel<64, 32, false, true, true><<<gB, 128>>>(
        nullptr, lw1, g2, bt2, lb1, lw2, lb2, out, N, 0, -1);
}